// round 2
// baseline (speedup 1.0000x reference)
#include <cuda_runtime.h>
#include <math.h>

#define THREADS 512

__global__ void wrpl_zero_out(float* out) {
    if (threadIdx.x == 0 && blockIdx.x == 0) out[0] = 0.0f;
}

__global__ __launch_bounds__(THREADS)
void wrpl_row_kernel(const float* __restrict__ scores,
                     const int* __restrict__ targets,
                     float* __restrict__ out,
                     int B, int C)
{
    const int row = blockIdx.x;
    const float* s = scores + (size_t)row * (size_t)C;
    const int t = targets[row];

    // broadcast load of ground-truth score (same address across warp -> 1 transaction)
    const float gt  = __ldg(s + t);
    const float thr = gt - 1.0f;   // l > 0  <=>  s > gt - 1

    int   cnt_gt  = 0;   // #{ s_j > gt }            -> rank
    int   cnt_eq  = 0;   // #{ s_j == gt, j < t }    -> stable-sort tie break
    int   cnt_pos = 0;   // #{ s_j > thr }           (includes j==t, corrected later)
    float hinge   = 0.0f;

    const int C4 = C >> 2;
    const float4* s4 = reinterpret_cast<const float4*>(s);

    for (int j4 = threadIdx.x; j4 < C4; j4 += THREADS) {
        float4 v = __ldg(s4 + j4);
        int base = j4 << 2;
        {
            float x = v.x; int idx = base + 0;
            cnt_gt += (x > gt);
            cnt_eq += ((x == gt) && (idx < t));
            if (x > thr) { cnt_pos++; hinge += (x - thr); }
        }
        {
            float x = v.y; int idx = base + 1;
            cnt_gt += (x > gt);
            cnt_eq += ((x == gt) && (idx < t));
            if (x > thr) { cnt_pos++; hinge += (x - thr); }
        }
        {
            float x = v.z; int idx = base + 2;
            cnt_gt += (x > gt);
            cnt_eq += ((x == gt) && (idx < t));
            if (x > thr) { cnt_pos++; hinge += (x - thr); }
        }
        {
            float x = v.w; int idx = base + 3;
            cnt_gt += (x > gt);
            cnt_eq += ((x == gt) && (idx < t));
            if (x > thr) { cnt_pos++; hinge += (x - thr); }
        }
    }
    // scalar tail (C not multiple of 4)
    for (int idx = (C4 << 2) + threadIdx.x; idx < C; idx += THREADS) {
        float x = __ldg(s + idx);
        cnt_gt += (x > gt);
        cnt_eq += ((x == gt) && (idx < t));
        if (x > thr) { cnt_pos++; hinge += (x - thr); }
    }

    // ---- block reduction: warp shuffle then shared ----
    const unsigned FULL = 0xFFFFFFFFu;
    #pragma unroll
    for (int off = 16; off > 0; off >>= 1) {
        cnt_gt  += __shfl_down_sync(FULL, cnt_gt,  off);
        cnt_eq  += __shfl_down_sync(FULL, cnt_eq,  off);
        cnt_pos += __shfl_down_sync(FULL, cnt_pos, off);
        hinge   += __shfl_down_sync(FULL, hinge,   off);
    }

    __shared__ int   sh_gt [THREADS / 32];
    __shared__ int   sh_eq [THREADS / 32];
    __shared__ int   sh_pos[THREADS / 32];
    __shared__ float sh_hg [THREADS / 32];

    const int lane = threadIdx.x & 31;
    const int wid  = threadIdx.x >> 5;
    if (lane == 0) {
        sh_gt[wid]  = cnt_gt;
        sh_eq[wid]  = cnt_eq;
        sh_pos[wid] = cnt_pos;
        sh_hg[wid]  = hinge;
    }
    __syncthreads();

    if (threadIdx.x == 0) {
        int   g = 0, e = 0, p = 0;
        float h = 0.0f;
        #pragma unroll
        for (int i = 0; i < THREADS / 32; i++) {
            g += sh_gt[i]; e += sh_eq[i]; p += sh_pos[i]; h += sh_hg[i];
        }

        // remove the j == t contribution (s_t == gt > thr always)
        p -= 1;
        h -= (gt - thr);   // exact value that was added in the loop

        const int rank = g + e + 1;

        // harmonic number H(rank)
        double H;
        if (rank <= 64) {
            H = 0.0;
            for (int i = 1; i <= rank; i++) H += 1.0 / (double)i;
        } else {
            double n  = (double)rank;
            double n2 = n * n;
            H = log(n) + 0.57721566490153286
              + 1.0 / (2.0 * n) - 1.0 / (12.0 * n2) + 1.0 / (120.0 * n2 * n2);
        }

        float npos = (float)p + 1e-7f;
        float loss = (float)H / npos * h;
        atomicAdd(out, loss / (float)B);
    }
}

extern "C" void kernel_launch(void* const* d_in, const int* in_sizes, int n_in,
                              void* d_out, int out_size)
{
    const float* scores  = (const float*)d_in[0];
    const int*   targets = (const int*)d_in[1];
    float*       out     = (float*)d_out;

    const int B = in_sizes[1];
    const int C = in_sizes[0] / B;

    wrpl_zero_out<<<1, 32>>>(out);
    wrpl_row_kernel<<<B, THREADS>>>(scores, targets, out, B, C);
}

// round 3
// speedup vs baseline: 1.0874x; 1.0874x over previous
#include <cuda_runtime.h>
#include <math.h>

#define THREADS 256

__global__ void wrpl_zero_out(float* out) {
    if (threadIdx.x == 0 && blockIdx.x == 0) out[0] = 0.0f;
}

// Process float4 range [lo, hi) with comparison (GE ? x>=gt : x>gt) for rank,
// plus hinge stats (cnt_pos, sum of x where x > thr).
template<bool GE>
__device__ __forceinline__ void scan_range(const float4* __restrict__ s4,
                                           int lo, int hi,
                                           float gt, float thr,
                                           int& cnt_rank, int& cnt_pos, float& xsum)
{
#define PROC(xv)                                              \
    {                                                         \
        float x = (xv);                                       \
        cnt_rank += GE ? (x >= gt) : (x > gt);                \
        bool p = (x > thr);                                   \
        cnt_pos += p;                                         \
        if (p) xsum += x;                                     \
    }

    int i = lo + threadIdx.x;
    // batched: 4 independent coalesced LDG.128 in flight
    for (; i + 3 * THREADS < hi; i += 4 * THREADS) {
        float4 a = __ldg(s4 + i);
        float4 b = __ldg(s4 + i + THREADS);
        float4 c = __ldg(s4 + i + 2 * THREADS);
        float4 d = __ldg(s4 + i + 3 * THREADS);
        PROC(a.x) PROC(a.y) PROC(a.z) PROC(a.w)
        PROC(b.x) PROC(b.y) PROC(b.z) PROC(b.w)
        PROC(c.x) PROC(c.y) PROC(c.z) PROC(c.w)
        PROC(d.x) PROC(d.y) PROC(d.z) PROC(d.w)
    }
    for (; i < hi; i += THREADS) {
        float4 a = __ldg(s4 + i);
        PROC(a.x) PROC(a.y) PROC(a.z) PROC(a.w)
    }
#undef PROC
}

__global__ __launch_bounds__(THREADS)
void wrpl_row_kernel(const float* __restrict__ scores,
                     const int* __restrict__ targets,
                     float* __restrict__ out,
                     int B, int C)
{
    const int row = blockIdx.x;
    const float* s = scores + (size_t)row * (size_t)C;
    const int t = targets[row];

    const float gt  = __ldg(s + t);
    const float thr = gt - 1.0f;   // l > 0  <=>  s > gt - 1

    const int C4  = C >> 2;        // C is a multiple of 4 here (32000)
    const int tb  = t >> 2;        // boundary float4 index containing j == t
    const float4* s4 = reinterpret_cast<const float4*>(s);

    int   cnt_rank = 0;   // #{j<t: s_j >= gt} + #{j>t: s_j > gt}  -> rank-1
    int   cnt_pos  = 0;   // #{j != t : s_j > thr}
    float xsum     = 0.0f;

    // Range A: float4 vecs [0, tb): all idx < t  -> use >=
    scan_range<true >(s4, 0,      tb, gt, thr, cnt_rank, cnt_pos, xsum);
    // Range B: float4 vecs (tb, C4): all idx > t -> use >
    scan_range<false>(s4, tb + 1, C4, gt, thr, cnt_rank, cnt_pos, xsum);

    // Boundary vector (contains j == t): scalar, thread 0 only
    if (threadIdx.x == 0) {
        int base = tb << 2;
        int end  = min(base + 4, C);
        for (int idx = base; idx < end; idx++) {
            if (idx == t) continue;          // j == t excluded by mask
            float x = __ldg(s + idx);
            cnt_rank += (idx < t) ? (x >= gt) : (x > gt);
            bool p = (x > thr);
            cnt_pos += p;
            if (p) xsum += x;
        }
    }

    // ---- block reduction ----
    const unsigned FULL = 0xFFFFFFFFu;
    #pragma unroll
    for (int off = 16; off > 0; off >>= 1) {
        cnt_rank += __shfl_down_sync(FULL, cnt_rank, off);
        cnt_pos  += __shfl_down_sync(FULL, cnt_pos,  off);
        xsum     += __shfl_down_sync(FULL, xsum,     off);
    }

    __shared__ int   sh_rk [THREADS / 32];
    __shared__ int   sh_pos[THREADS / 32];
    __shared__ float sh_xs [THREADS / 32];

    const int lane = threadIdx.x & 31;
    const int wid  = threadIdx.x >> 5;
    if (lane == 0) {
        sh_rk[wid]  = cnt_rank;
        sh_pos[wid] = cnt_pos;
        sh_xs[wid]  = xsum;
    }
    __syncthreads();

    if (threadIdx.x == 0) {
        int   rk = 0, p = 0;
        float xs = 0.0f;
        #pragma unroll
        for (int i = 0; i < THREADS / 32; i++) {
            rk += sh_rk[i]; p += sh_pos[i]; xs += sh_xs[i];
        }

        const int rank = rk + 1;
        const float hinge = xs - (float)p * thr;

        // harmonic number H(rank)
        double H;
        if (rank <= 64) {
            H = 0.0;
            for (int i = 1; i <= rank; i++) H += 1.0 / (double)i;
        } else {
            double n  = (double)rank;
            double n2 = n * n;
            H = log(n) + 0.57721566490153286
              + 1.0 / (2.0 * n) - 1.0 / (12.0 * n2) + 1.0 / (120.0 * n2 * n2);
        }

        float npos = (float)p + 1e-7f;
        float loss = (float)H / npos * hinge;
        atomicAdd(out, loss / (float)B);
    }
}

extern "C" void kernel_launch(void* const* d_in, const int* in_sizes, int n_in,
                              void* d_out, int out_size)
{
    const float* scores  = (const float*)d_in[0];
    const int*   targets = (const int*)d_in[1];
    float*       out     = (float*)d_out;

    const int B = in_sizes[1];
    const int C = in_sizes[0] / B;

    wrpl_zero_out<<<1, 32>>>(out);
    wrpl_row_kernel<<<B, THREADS>>>(scores, targets, out, B, C);
}

// round 4
// speedup vs baseline: 1.1333x; 1.0423x over previous
#include <cuda_runtime.h>
#include <math.h>

#define THREADS 256
#define BATCH 8

__global__ void wrpl_zero_out(float* out) {
    if (threadIdx.x == 0 && blockIdx.x == 0) out[0] = 0.0f;
}

// Process float4 range [lo, hi) with comparison (GE ? x>=gt : x>gt) for rank,
// plus hinge stats (cnt_pos, sum of x where x > thr).
template<bool GE>
__device__ __forceinline__ void scan_range(const float4* __restrict__ s4,
                                           int lo, int hi,
                                           float gt, float thr,
                                           int& cnt_rank, int& cnt_pos, float& xsum)
{
#define PROC(xv)                                              \
    {                                                         \
        float x = (xv);                                       \
        cnt_rank += GE ? (x >= gt) : (x > gt);                \
        bool p = (x > thr);                                   \
        cnt_pos += p;                                         \
        if (p) xsum += x;                                     \
    }

    int i = lo + threadIdx.x;
    // deep batch: BATCH independent coalesced LDG.128 in flight before compute
    for (; i + (BATCH - 1) * THREADS < hi; i += BATCH * THREADS) {
        float4 v[BATCH];
        #pragma unroll
        for (int k = 0; k < BATCH; k++)
            v[k] = __ldg(s4 + i + k * THREADS);
        #pragma unroll
        for (int k = 0; k < BATCH; k++) {
            PROC(v[k].x) PROC(v[k].y) PROC(v[k].z) PROC(v[k].w)
        }
    }
    for (; i < hi; i += THREADS) {
        float4 a = __ldg(s4 + i);
        PROC(a.x) PROC(a.y) PROC(a.z) PROC(a.w)
    }
#undef PROC
}

__global__ __launch_bounds__(THREADS)
void wrpl_row_kernel(const float* __restrict__ scores,
                     const int* __restrict__ targets,
                     float* __restrict__ out,
                     int B, int C)
{
    const int row = blockIdx.x;
    const float* s = scores + (size_t)row * (size_t)C;
    const int t = targets[row];

    const float gt  = __ldg(s + t);
    const float thr = gt - 1.0f;   // l > 0  <=>  s > gt - 1

    const int C4  = C >> 2;        // C is a multiple of 4 (32000)
    const int tb  = t >> 2;        // boundary float4 index containing j == t
    const float4* s4 = reinterpret_cast<const float4*>(s);

    int   cnt_rank = 0;   // #{j<t: s_j >= gt} + #{j>t: s_j > gt}  -> rank-1
    int   cnt_pos  = 0;   // #{j != t : s_j > thr}
    float xsum     = 0.0f;

    // Range A: float4 vecs [0, tb): all idx < t  -> use >=
    scan_range<true >(s4, 0,      tb, gt, thr, cnt_rank, cnt_pos, xsum);
    // Range B: float4 vecs (tb, C4): all idx > t -> use >
    scan_range<false>(s4, tb + 1, C4, gt, thr, cnt_rank, cnt_pos, xsum);

    // Boundary vector (contains j == t): scalar, thread 0 only
    if (threadIdx.x == 0) {
        int base = tb << 2;
        int end  = min(base + 4, C);
        for (int idx = base; idx < end; idx++) {
            if (idx == t) continue;          // j == t excluded by mask
            float x = __ldg(s + idx);
            cnt_rank += (idx < t) ? (x >= gt) : (x > gt);
            bool p = (x > thr);
            cnt_pos += p;
            if (p) xsum += x;
        }
    }

    // ---- block reduction ----
    const unsigned FULL = 0xFFFFFFFFu;
    #pragma unroll
    for (int off = 16; off > 0; off >>= 1) {
        cnt_rank += __shfl_down_sync(FULL, cnt_rank, off);
        cnt_pos  += __shfl_down_sync(FULL, cnt_pos,  off);
        xsum     += __shfl_down_sync(FULL, xsum,     off);
    }

    __shared__ int   sh_rk [THREADS / 32];
    __shared__ int   sh_pos[THREADS / 32];
    __shared__ float sh_xs [THREADS / 32];

    const int lane = threadIdx.x & 31;
    const int wid  = threadIdx.x >> 5;
    if (lane == 0) {
        sh_rk[wid]  = cnt_rank;
        sh_pos[wid] = cnt_pos;
        sh_xs[wid]  = xsum;
    }
    __syncthreads();

    if (threadIdx.x == 0) {
        int   rk = 0, p = 0;
        float xs = 0.0f;
        #pragma unroll
        for (int i = 0; i < THREADS / 32; i++) {
            rk += sh_rk[i]; p += sh_pos[i]; xs += sh_xs[i];
        }

        const int rank = rk + 1;
        const float hinge = xs - (float)p * thr;

        // harmonic number H(rank)
        double H;
        if (rank <= 64) {
            H = 0.0;
            for (int i = 1; i <= rank; i++) H += 1.0 / (double)i;
        } else {
            double n  = (double)rank;
            double n2 = n * n;
            H = log(n) + 0.57721566490153286
              + 1.0 / (2.0 * n) - 1.0 / (12.0 * n2) + 1.0 / (120.0 * n2 * n2);
        }

        float npos = (float)p + 1e-7f;
        float loss = (float)H / npos * hinge;
        atomicAdd(out, loss / (float)B);
    }
}

extern "C" void kernel_launch(void* const* d_in, const int* in_sizes, int n_in,
                              void* d_out, int out_size)
{
    const float* scores  = (const float*)d_in[0];
    const int*   targets = (const int*)d_in[1];
    float*       out     = (float*)d_out;

    const int B = in_sizes[1];
    const int C = in_sizes[0] / B;

    wrpl_zero_out<<<1, 32>>>(out);
    wrpl_row_kernel<<<B, THREADS>>>(scores, targets, out, B, C);
}

// round 5
// speedup vs baseline: 1.2372x; 1.0916x over previous
#include <cuda_runtime.h>
#include <math.h>

#define THREADS 256
#define STAGES  8                       // ring depth; STAGES-2 tiles in flight
#define CPT     THREADS                 // chunks (16B) per tile = 1 per thread

__global__ void wrpl_zero_out(float* out) {
    if (threadIdx.x == 0 && blockIdx.x == 0) out[0] = 0.0f;
}

__device__ __forceinline__ void cp_async16(void* smem_dst, const void* gsrc) {
    unsigned saddr = (unsigned)__cvta_generic_to_shared(smem_dst);
    asm volatile("cp.async.cg.shared.global [%0], [%1], 16;\n"
                 :: "r"(saddr), "l"(gsrc));
}
__device__ __forceinline__ void cp_async_commit() {
    asm volatile("cp.async.commit_group;\n" ::: "memory");
}
template<int N>
__device__ __forceinline__ void cp_async_wait() {
    asm volatile("cp.async.wait_group %0;\n" :: "n"(N) : "memory");
}

__global__ __launch_bounds__(THREADS)
void wrpl_row_kernel(const float* __restrict__ scores,
                     const int* __restrict__ targets,
                     float* __restrict__ out,
                     int B, int C)
{
    // Each thread owns one 16B slot per stage -> no cross-thread smem sharing,
    // no __syncthreads in the streaming loop. wait_group orders own write/read.
    __shared__ float4 buf[STAGES][CPT];

    const int row = blockIdx.x;
    const float* s = scores + (size_t)row * (size_t)C;
    const int t = targets[row];

    const float gt  = __ldg(s + t);
    const float thr = gt - 1.0f;        // l > 0  <=>  s > gt - 1

    const int nChunks = C >> 2;         // float4 chunks per row (C % 4 == 0)
    const int nTiles  = (nChunks + CPT - 1) / CPT;
    const int tb      = t >> 2;         // chunk containing the target

    const float4* s4 = reinterpret_cast<const float4*>(s);
    const int td = threadIdx.x;

    int   cnt_rank = 0;   // #{j<t: s_j >= gt} + #{j>t: s_j > gt} = rank-1
    int   cnt_pos  = 0;   // #{j != t : s_j > thr}
    float xsum     = 0.0f;

    // ---- prologue: fill STAGES-2 stages ----
    #pragma unroll
    for (int pt = 0; pt < STAGES - 2; ++pt) {
        int c4 = pt * CPT + td;
        if (pt < nTiles && c4 < nChunks)
            cp_async16(&buf[pt][td], s4 + c4);
        cp_async_commit();
    }

#define PROC_GE(xv) { float x = (xv); cnt_rank += (x >= gt); bool p = (x > thr); cnt_pos += p; if (p) xsum += x; }
#define PROC_GT(xv) { float x = (xv); cnt_rank += (x >  gt); bool p = (x > thr); cnt_pos += p; if (p) xsum += x; }

    // ---- streaming loop: 1 issue + 1 wait per tile, no barriers ----
    for (int tile = 0; tile < nTiles; ++tile) {
        const int it = tile + STAGES - 2;
        if (it < nTiles) {
            int c4i = it * CPT + td;
            if (c4i < nChunks)
                cp_async16(&buf[it % STAGES][td], s4 + c4i);
        }
        cp_async_commit();
        cp_async_wait<STAGES - 2>();     // own tile `tile` is complete

        const int c4 = tile * CPT + td;
        if (c4 < nChunks) {
            float4 v = buf[tile % STAGES][td];
            if (c4 < tb) {               // all idx < t
                PROC_GE(v.x) PROC_GE(v.y) PROC_GE(v.z) PROC_GE(v.w)
            } else if (c4 > tb) {        // all idx > t
                PROC_GT(v.x) PROC_GT(v.y) PROC_GT(v.z) PROC_GT(v.w)
            } else {                     // boundary chunk: contains j == t
                const float xv[4] = {v.x, v.y, v.z, v.w};
                const int base = c4 << 2;
                #pragma unroll
                for (int e = 0; e < 4; ++e) {
                    int idx = base + e;
                    if (idx == t) continue;
                    float x = xv[e];
                    cnt_rank += (idx < t) ? (x >= gt) : (x > gt);
                    bool p = (x > thr);
                    cnt_pos += p;
                    if (p) xsum += x;
                }
            }
        }
    }
#undef PROC_GE
#undef PROC_GT

    // ---- block reduction ----
    const unsigned FULL = 0xFFFFFFFFu;
    #pragma unroll
    for (int off = 16; off > 0; off >>= 1) {
        cnt_rank += __shfl_down_sync(FULL, cnt_rank, off);
        cnt_pos  += __shfl_down_sync(FULL, cnt_pos,  off);
        xsum     += __shfl_down_sync(FULL, xsum,     off);
    }

    __shared__ int   sh_rk [THREADS / 32];
    __shared__ int   sh_pos[THREADS / 32];
    __shared__ float sh_xs [THREADS / 32];

    const int lane = td & 31;
    const int wid  = td >> 5;
    if (lane == 0) {
        sh_rk[wid]  = cnt_rank;
        sh_pos[wid] = cnt_pos;
        sh_xs[wid]  = xsum;
    }
    __syncthreads();

    if (td == 0) {
        int   rk = 0, p = 0;
        float xs = 0.0f;
        #pragma unroll
        for (int i = 0; i < THREADS / 32; i++) {
            rk += sh_rk[i]; p += sh_pos[i]; xs += sh_xs[i];
        }

        const int rank = rk + 1;
        const float hinge = xs - (float)p * thr;

        // harmonic number H(rank)
        double H;
        if (rank <= 64) {
            H = 0.0;
            for (int i = 1; i <= rank; i++) H += 1.0 / (double)i;
        } else {
            double n  = (double)rank;
            double n2 = n * n;
            H = log(n) + 0.57721566490153286
              + 1.0 / (2.0 * n) - 1.0 / (12.0 * n2) + 1.0 / (120.0 * n2 * n2);
        }

        float npos = (float)p + 1e-7f;
        float loss = (float)H / npos * hinge;
        atomicAdd(out, loss / (float)B);
    }
}

extern "C" void kernel_launch(void* const* d_in, const int* in_sizes, int n_in,
                              void* d_out, int out_size)
{
    const float* scores  = (const float*)d_in[0];
    const int*   targets = (const int*)d_in[1];
    float*       out     = (float*)d_out;

    const int B = in_sizes[1];
    const int C = in_sizes[0] / B;

    wrpl_zero_out<<<1, 32>>>(out);
    wrpl_row_kernel<<<B, THREADS>>>(scores, targets, out, B, C);
}